// round 11
// baseline (speedup 1.0000x reference)
#include <cuda_runtime.h>
#include <math.h>

#define STEP_SIZE 0.1f
#define D_LIMIT   0.05f
#define EPS_V     1e-9f

__device__ __forceinline__ float rcp_approx(float x) {
    float r; asm("rcp.approx.f32 %0, %1;" : "=f"(r) : "f"(x)); return r;
}
__device__ __forceinline__ float sqrt_approx(float x) {
    float r; asm("sqrt.approx.f32 %0, %1;" : "=f"(r) : "f"(x)); return r;
}

// One warp per batch element. lane = robot link index (R == 32).
// B = 8192, R = 32, P = 16.  8 warps / 256-thread block, 1024 blocks.

#define WARPS_PER_BLOCK 8

__global__ __launch_bounds__(256, 8)
void safety_layer_kernel(const float* __restrict__ joint_state,     // [B,R]
                         const float* __restrict__ action_nominal,  // [B,R]
                         const float* __restrict__ link_lengths,    // [R]
                         const float* __restrict__ robot_radii,     // [R]
                         const float* __restrict__ p_start,         // [B,P,3]
                         const float* __restrict__ p_end,           // [B,P,3]
                         const float* __restrict__ p_radii,         // [B,P]
                         const float* __restrict__ log_lambda,      // [1]
                         float* __restrict__ out_action,            // [B,R]
                         float* __restrict__ out_penalty,           // [B]
                         float* __restrict__ out_mind,              // [B]
                         int B)
{
    const int R = 32;
    const int P = 16;
    const unsigned FULL = 0xffffffffu;

    // per-warp capsule stage: A={p2x,p2y,p2z,pr} B={d2x,d2y,d2z,g} C={e,inv_e}
    __shared__ float4 sA[WARPS_PER_BLOCK][P];
    __shared__ float4 sB[WARPS_PER_BLOCK][P];
    __shared__ float2 sC[WARPS_PER_BLOCK][P];

    int wid_in_blk = threadIdx.x >> 5;
    int gwarp = (blockIdx.x * blockDim.x + threadIdx.x) >> 5;
    int lane  = threadIdx.x & 31;
    if (gwarp >= B) return;
    const int b = gwarp;

    // ---- load per-lane joint data, pass through action ----
    float an = action_nominal[b * R + lane];
    out_action[b * R + lane] = an;
    float q = joint_state[b * R + lane] + an * STEP_SIZE;

    // ---- per-capsule precompute into smem (lanes 0..15) ----
    {
        const float* ps_base = p_start + (size_t)b * P * 3;
        const float* pe_base = p_end   + (size_t)b * P * 3;
        const float* pr_base = p_radii + (size_t)b * P;
        int cp = lane & 15;
        float p2x = ps_base[cp * 3 + 0];
        float p2y = ps_base[cp * 3 + 1];
        float p2z = ps_base[cp * 3 + 2];
        float d2x = pe_base[cp * 3 + 0] - p2x;
        float d2y = pe_base[cp * 3 + 1] - p2y;
        float d2z = pe_base[cp * 3 + 2] - p2z;
        float e   = d2x * d2x + d2y * d2y + d2z * d2z;
        float ie  = rcp_approx(e);                          // unguarded (see notes)
        float g   = d2x * p2x + d2y * p2y + d2z * p2z;      // d2 . p2
        if (lane < 16) {
            sA[wid_in_blk][cp] = make_float4(p2x, p2y, p2z, pr_base[cp]);
            sB[wid_in_blk][cp] = make_float4(d2x, d2y, d2z, g);
            sC[wid_in_blk][cp] = make_float2(e, ie);
        }
    }

    // ---- theta = inclusive cumsum of q across lanes ----
    float theta = q;
    #pragma unroll
    for (int off = 1; off < 32; off <<= 1) {
        float v = __shfl_up_sync(FULL, theta, off);
        if (lane >= off) theta += v;
    }

    // ---- link vector = L * (cos, sin); fast HW sincos ----
    float L = link_lengths[lane];
    float sth, cth;
    __sincosf(theta, &sth, &cth);
    float px = L * cth, py = L * sth;

    // inclusive 2D prefix sum -> chain end points
    #pragma unroll
    for (int off = 1; off < 32; off <<= 1) {
        float ax = __shfl_up_sync(FULL, px, off);
        float ay = __shfl_up_sync(FULL, py, off);
        if (lane >= off) { px += ax; py += ay; }
    }
    float sx = __shfl_up_sync(FULL, px, 1);
    float sy = __shfl_up_sync(FULL, py, 1);
    if (lane == 0) { sx = 0.0f; sy = 0.0f; }

    // robot segment: p1=(sx,sy,0), q1=(px,py,0); d1 = q1-p1 (z=0)
    float d1x = px - sx;
    float d1y = py - sy;
    float a   = d1x * d1x + d1y * d1y;
    float inv_a = rcp_approx(a);                            // unguarded
    float h1  = d1x * sx + d1y * sy;                        // d1 . s1 (invariant)

    __syncwarp();

    float mind = INFINITY;   // min over p of (dist - pr); rrad folded after loop

    #pragma unroll 8
    for (int p = 0; p < P; p++) {
        float4 A  = sA[wid_in_blk][p];   // p2x p2y p2z pr
        float4 Bv = sB[wid_in_blk][p];   // d2x d2y d2z g
        float2 C  = sC[wid_in_blk][p];   // e, inv_e
        float p2x = A.x, p2y = A.y, p2z = A.z, pr = A.w;
        float d2x = Bv.x, d2y = Bv.y, d2z = Bv.z, g = Bv.w;
        float e = C.x, inv_e = C.y;

        float f  = fmaf(d2x, sx, fmaf(d2y, sy, -g));        // d2 . r
        float c  = h1 - fmaf(d1x, p2x, d1y * p2y);          // d1 . r
        float bb = fmaf(d1x, d2x, d1y * d2y);

        float denom = fmaf(a, e, -bb * bb);
        // saturate folds clamp into the producing op; rcp(0)->inf->sat, NaN->0
        float s = __saturatef(fmaf(bb, f, -c * e) * rcp_approx(denom));

        float t   = fmaf(bb, s, f) * inv_e;
        float t_c = __saturatef(t);
        float s_adj = __saturatef(fmaf(bb, t_c, -c) * inv_a);
        s = (t != t_c) ? s_adj : s;

        float c1x = fmaf(d1x, s, sx);
        float c1y = fmaf(d1y, s, sy);
        float c2x = fmaf(d2x, t_c, p2x);
        float c2y = fmaf(d2y, t_c, p2y);
        float c2z = fmaf(d2z, t_c, p2z);

        float dx = c1x - c2x;
        float dy = c1y - c2y;
        float dist = sqrt_approx(fmaf(dx, dx, fmaf(dy, dy, fmaf(c2z, c2z, 1e-12f))));

        mind = fminf(mind, dist - pr);
    }

    mind -= robot_radii[lane];   // lane-constant offset folded out of the loop

    // ---- warp min-reduce over lanes (links) ----
    #pragma unroll
    for (int off = 16; off > 0; off >>= 1)
        mind = fminf(mind, __shfl_xor_sync(FULL, mind, off));

    if (lane == 0) {
        float lam = __expf(log_lambda[0]);
        float magnitude = lam * (D_LIMIT - mind);
        out_penalty[b] = (mind < D_LIMIT) ? magnitude : 0.0f;
        out_mind[b]    = mind;
    }
}

extern "C" void kernel_launch(void* const* d_in, const int* in_sizes, int n_in,
                              void* d_out, int out_size)
{
    const float* joint_state    = (const float*)d_in[0];
    const float* action_nominal = (const float*)d_in[1];
    const float* link_lengths   = (const float*)d_in[2];
    const float* robot_radii    = (const float*)d_in[3];
    const float* p_start        = (const float*)d_in[4];
    const float* p_end          = (const float*)d_in[5];
    const float* p_radii        = (const float*)d_in[6];
    const float* log_lambda     = (const float*)d_in[7];

    const int R = 32;
    int B = in_sizes[0] / R;   // 8192

    float* out = (float*)d_out;
    float* out_action  = out;                      // [B,R]
    float* out_penalty = out + (size_t)B * R;      // [B]
    float* out_mind    = out + (size_t)B * R + B;  // [B]

    int blocks = (B + WARPS_PER_BLOCK - 1) / WARPS_PER_BLOCK;   // 1024
    safety_layer_kernel<<<blocks, WARPS_PER_BLOCK * 32>>>(
        joint_state, action_nominal, link_lengths, robot_radii,
        p_start, p_end, p_radii, log_lambda,
        out_action, out_penalty, out_mind, B);
}

// round 13
// speedup vs baseline: 1.0025x; 1.0025x over previous
#include <cuda_runtime.h>
#include <math.h>

#define STEP_SIZE 0.1f
#define D_LIMIT   0.05f
#define EPS_V     1e-9f

__device__ __forceinline__ float rcp_approx(float x) {
    float r; asm("rcp.approx.f32 %0, %1;" : "=f"(r) : "f"(x)); return r;
}
__device__ __forceinline__ float sqrt_approx(float x) {
    float r; asm("sqrt.approx.f32 %0, %1;" : "=f"(r) : "f"(x)); return r;
}

// One warp per batch element. lane = robot link index (R == 32).
// B = 8192, R = 32, P = 16.  8 warps / 256-thread block, 1024 blocks.

#define WARPS_PER_BLOCK 8

__global__ __launch_bounds__(256, 8)
void safety_layer_kernel(const float* __restrict__ joint_state,     // [B,R]
                         const float* __restrict__ action_nominal,  // [B,R]
                         const float* __restrict__ link_lengths,    // [R]
                         const float* __restrict__ robot_radii,     // [R]
                         const float* __restrict__ p_start,         // [B,P,3]
                         const float* __restrict__ p_end,           // [B,P,3]
                         const float* __restrict__ p_radii,         // [B,P]
                         const float* __restrict__ log_lambda,      // [1]
                         float* __restrict__ out_action,            // [B,R]
                         float* __restrict__ out_penalty,           // [B]
                         float* __restrict__ out_mind)              // [B]
{
    const int R = 32;
    const int P = 16;
    const unsigned FULL = 0xffffffffu;

    // per-warp capsule stage: A={p2x,p2y,p2z,pr} B={d2x,d2y,d2z,g} C={inv_e}
    __shared__ float4 sA[WARPS_PER_BLOCK][P];
    __shared__ float4 sB[WARPS_PER_BLOCK][P];
    __shared__ float  sC[WARPS_PER_BLOCK][P];

    int wid_in_blk = threadIdx.x >> 5;
    int gwarp = (blockIdx.x * blockDim.x + threadIdx.x) >> 5;
    int lane  = threadIdx.x & 31;
    const int b = gwarp;                        // grid exactly covers B

    // ---- load per-lane joint data, pass through action ----
    float an = action_nominal[b * R + lane];
    out_action[b * R + lane] = an;
    float q = joint_state[b * R + lane] + an * STEP_SIZE;

    // ---- per-capsule precompute into smem (lanes 0..15) ----
    {
        const float* ps_base = p_start + (size_t)b * P * 3;
        const float* pe_base = p_end   + (size_t)b * P * 3;
        const float* pr_base = p_radii + (size_t)b * P;
        int cp = lane & 15;
        float p2x = ps_base[cp * 3 + 0];
        float p2y = ps_base[cp * 3 + 1];
        float p2z = ps_base[cp * 3 + 2];
        float d2x = pe_base[cp * 3 + 0] - p2x;
        float d2y = pe_base[cp * 3 + 1] - p2y;
        float d2z = pe_base[cp * 3 + 2] - p2z;
        float e   = d2x * d2x + d2y * d2y + d2z * d2z;
        float ie  = rcp_approx(e);                          // unguarded (validated R11)
        float g   = d2x * p2x + d2y * p2y + d2z * p2z;      // d2 . p2
        if (lane < 16) {
            sA[wid_in_blk][cp] = make_float4(p2x, p2y, p2z, pr_base[cp]);
            sB[wid_in_blk][cp] = make_float4(d2x, d2y, d2z, g);
            sC[wid_in_blk][cp] = ie;
        }
    }

    // ---- theta = inclusive cumsum of q across lanes ----
    float theta = q;
    #pragma unroll
    for (int off = 1; off < 32; off <<= 1) {
        float v = __shfl_up_sync(FULL, theta, off);
        if (lane >= off) theta += v;
    }

    // ---- link vector = L * (cos, sin); fast HW sincos ----
    float L = link_lengths[lane];
    float sth, cth;
    __sincosf(theta, &sth, &cth);
    float px = L * cth, py = L * sth;

    // inclusive 2D prefix sum -> chain end points
    #pragma unroll
    for (int off = 1; off < 32; off <<= 1) {
        float ax = __shfl_up_sync(FULL, px, off);
        float ay = __shfl_up_sync(FULL, py, off);
        if (lane >= off) { px += ax; py += ay; }
    }
    float sx = __shfl_up_sync(FULL, px, 1);
    float sy = __shfl_up_sync(FULL, py, 1);
    if (lane == 0) { sx = 0.0f; sy = 0.0f; }

    // robot segment: p1=(sx,sy,0), q1=(px,py,0); d1 = q1-p1 (z=0)
    float d1x = px - sx;
    float d1y = py - sy;
    float nd1x = -d1x, nd1y = -d1y;             // for 2-FFMA c computation
    float a   = d1x * d1x + d1y * d1y;
    float inv_a = rcp_approx(a);                // unguarded
    float h1  = d1x * sx + d1y * sy;            // d1 . s1 (invariant)

    __syncwarp();

    float mind = INFINITY;   // min over p of (dist - pr); rrad folded after loop

    #pragma unroll 8
    for (int p = 0; p < P; p++) {
        float4 A  = sA[wid_in_blk][p];   // p2x p2y p2z pr
        float4 Bv = sB[wid_in_blk][p];   // d2x d2y d2z g
        float inv_e = sC[wid_in_blk][p];
        float p2x = A.x, p2y = A.y, p2z = A.z, pr = A.w;
        float d2x = Bv.x, d2y = Bv.y, d2z = Bv.z, g = Bv.w;

        float f  = fmaf(d2x, sx, fmaf(d2y, sy, -g));          // d2 . r
        float c  = fmaf(nd1x, p2x, fmaf(nd1y, p2y, h1));      // d1 . r (2 FFMA)
        float bb = fmaf(d1x, d2x, d1y * d2y);

        // s = sat((bb*f - c*e)/(a*e - bb^2)); fold 1/e through (e > 0):
        float bi    = bb * inv_e;
        float s_num = fmaf(bi, f, -c);
        float s_den = fmaf(-bi, bb, a);
        float s = __saturatef(s_num * rcp_approx(s_den));

        float t   = fmaf(bb, s, f) * inv_e;
        float t_c = __saturatef(t);
        float s_adj = __saturatef(fmaf(bb, t_c, -c) * inv_a);
        s = (t != t_c) ? s_adj : s;

        float c1x = fmaf(d1x, s, sx);
        float c1y = fmaf(d1y, s, sy);
        float c2x = fmaf(d2x, t_c, p2x);
        float c2y = fmaf(d2y, t_c, p2y);
        float c2z = fmaf(d2z, t_c, p2z);

        float dx = c1x - c2x;
        float dy = c1y - c2y;
        float dist = sqrt_approx(fmaf(dx, dx, fmaf(dy, dy, fmaf(c2z, c2z, 1e-12f))));

        mind = fminf(mind, dist - pr);
    }

    mind -= robot_radii[lane];   // lane-constant offset folded out of the loop

    // ---- warp min-reduce over lanes (links) ----
    #pragma unroll
    for (int off = 16; off > 0; off >>= 1)
        mind = fminf(mind, __shfl_xor_sync(FULL, mind, off));

    if (lane == 0) {
        float lam = __expf(log_lambda[0]);
        float magnitude = lam * (D_LIMIT - mind);
        out_penalty[b] = (mind < D_LIMIT) ? magnitude : 0.0f;
        out_mind[b]    = mind;
    }
}

extern "C" void kernel_launch(void* const* d_in, const int* in_sizes, int n_in,
                              void* d_out, int out_size)
{
    const float* joint_state    = (const float*)d_in[0];
    const float* action_nominal = (const float*)d_in[1];
    const float* link_lengths   = (const float*)d_in[2];
    const float* robot_radii    = (const float*)d_in[3];
    const float* p_start        = (const float*)d_in[4];
    const float* p_end          = (const float*)d_in[5];
    const float* p_radii        = (const float*)d_in[6];
    const float* log_lambda     = (const float*)d_in[7];

    const int R = 32;
    int B = in_sizes[0] / R;   // 8192

    float* out = (float*)d_out;
    float* out_action  = out;                      // [B,R]
    float* out_penalty = out + (size_t)B * R;      // [B]
    float* out_mind    = out + (size_t)B * R + B;  // [B]

    int blocks = (B + WARPS_PER_BLOCK - 1) / WARPS_PER_BLOCK;   // 1024
    safety_layer_kernel<<<blocks, WARPS_PER_BLOCK * 32>>>(
        joint_state, action_nominal, link_lengths, robot_radii,
        p_start, p_end, p_radii, log_lambda,
        out_action, out_penalty, out_mind);
}

// round 14
// speedup vs baseline: 1.0226x; 1.0201x over previous
#include <cuda_runtime.h>
#include <math.h>

#define STEP_SIZE 0.1f
#define D_LIMIT   0.05f
#define EPS_V     1e-9f

__device__ __forceinline__ float rcp_approx(float x) {
    float r; asm("rcp.approx.f32 %0, %1;" : "=f"(r) : "f"(x)); return r;
}
__device__ __forceinline__ float sqrt_approx(float x) {
    float r; asm("sqrt.approx.f32 %0, %1;" : "=f"(r) : "f"(x)); return r;
}

// One warp per batch element. lane = robot link index (R == 32).
// B = 8192, R = 32, P = 16.  8 warps / 256-thread block, 1024 blocks.

#define WARPS_PER_BLOCK 8

__global__ __launch_bounds__(256, 8)
void safety_layer_kernel(const float* __restrict__ joint_state,     // [B,R]
                         const float* __restrict__ action_nominal,  // [B,R]
                         const float* __restrict__ link_lengths,    // [R]
                         const float* __restrict__ robot_radii,     // [R]
                         const float* __restrict__ p_start,         // [B,P,3]
                         const float* __restrict__ p_end,           // [B,P,3]
                         const float* __restrict__ p_radii,         // [B,P]
                         const float* __restrict__ log_lambda,      // [1]
                         float* __restrict__ out_action,            // [B,R]
                         float* __restrict__ out_penalty,           // [B]
                         float* __restrict__ out_mind)              // [B]
{
    const int R = 32;
    const int P = 16;
    const unsigned FULL = 0xffffffffu;

    // per-warp capsule stage: A={p2x,p2y,p2z,pr} B={d2x,d2y,d2z,g} C={e,inv_e}
    __shared__ float4 sA[WARPS_PER_BLOCK][P];
    __shared__ float4 sB[WARPS_PER_BLOCK][P];
    __shared__ float2 sC[WARPS_PER_BLOCK][P];

    int wid_in_blk = threadIdx.x >> 5;
    int gwarp = (blockIdx.x * blockDim.x + threadIdx.x) >> 5;
    int lane  = threadIdx.x & 31;
    const int b = gwarp;                        // grid exactly covers B

    // ---- load per-lane joint data, pass through action ----
    float an = action_nominal[b * R + lane];
    out_action[b * R + lane] = an;
    float q = joint_state[b * R + lane] + an * STEP_SIZE;

    // ---- per-capsule precompute, 2 lanes per capsule ----
    // even lane of pair: loads p_start + radius; odd lane: loads p_end.
    {
        const float* ps_base = p_start + (size_t)b * P * 3;
        const float* pe_base = p_end   + (size_t)b * P * 3;
        const float* pr_base = p_radii + (size_t)b * P;
        int cp   = lane >> 1;            // capsule id 0..15
        bool odd = lane & 1;
        const float* src = odd ? pe_base : ps_base;
        float vx = src[cp * 3 + 0];
        float vy = src[cp * 3 + 1];
        float vz = src[cp * 3 + 2];
        // even lane receives partner's p_end via shfl_down(1)
        float qx = __shfl_down_sync(FULL, vx, 1);
        float qy = __shfl_down_sync(FULL, vy, 1);
        float qz = __shfl_down_sync(FULL, vz, 1);
        if (!odd) {
            float p2x = vx, p2y = vy, p2z = vz;
            float d2x = qx - p2x;
            float d2y = qy - p2y;
            float d2z = qz - p2z;
            float e   = d2x * d2x + d2y * d2y + d2z * d2z;
            float ie  = rcp_approx(e);
            float g   = d2x * p2x + d2y * p2y + d2z * p2z;   // d2 . p2
            sA[wid_in_blk][cp] = make_float4(p2x, p2y, p2z, pr_base[cp]);
            sB[wid_in_blk][cp] = make_float4(d2x, d2y, d2z, g);
            sC[wid_in_blk][cp] = make_float2(e, ie);
        }
    }

    // ---- theta = inclusive cumsum of q across lanes ----
    float theta = q;
    #pragma unroll
    for (int off = 1; off < 32; off <<= 1) {
        float v = __shfl_up_sync(FULL, theta, off);
        if (lane >= off) theta += v;
    }

    // ---- link vector = L * (cos, sin); fast HW sincos ----
    float L = link_lengths[lane];
    float sth, cth;
    __sincosf(theta, &sth, &cth);
    float px = L * cth, py = L * sth;

    // inclusive 2D prefix sum -> chain end points
    #pragma unroll
    for (int off = 1; off < 32; off <<= 1) {
        float ax = __shfl_up_sync(FULL, px, off);
        float ay = __shfl_up_sync(FULL, py, off);
        if (lane >= off) { px += ax; py += ay; }
    }
    float sx = __shfl_up_sync(FULL, px, 1);
    float sy = __shfl_up_sync(FULL, py, 1);
    if (lane == 0) { sx = 0.0f; sy = 0.0f; }

    // robot segment: p1=(sx,sy,0), q1=(px,py,0); d1 = q1-p1 (z=0)
    float d1x = px - sx;
    float d1y = py - sy;
    float nd1x = -d1x, nd1y = -d1y;             // for 2-FFMA c computation
    float a   = d1x * d1x + d1y * d1y;
    float inv_a = rcp_approx(a);                // unguarded (validated)
    float h1  = d1x * sx + d1y * sy;            // d1 . s1 (invariant)

    __syncwarp();

    float mind = INFINITY;   // min over p of (dist - pr); rrad folded after loop

    #pragma unroll 8
    for (int p = 0; p < P; p++) {
        float4 A  = sA[wid_in_blk][p];   // p2x p2y p2z pr
        float4 Bv = sB[wid_in_blk][p];   // d2x d2y d2z g
        float2 C  = sC[wid_in_blk][p];   // e, inv_e
        float p2x = A.x, p2y = A.y, p2z = A.z, pr = A.w;
        float d2x = Bv.x, d2y = Bv.y, d2z = Bv.z, g = Bv.w;
        float e = C.x, inv_e = C.y;

        float f  = fmaf(d2x, sx, fmaf(d2y, sy, -g));          // d2 . r
        float c  = fmaf(nd1x, p2x, fmaf(nd1y, p2y, h1));      // d1 . r (2 FFMA)
        float bb = fmaf(d1x, d2x, d1y * d2y);

        // parallel-form solve: numerator & denominator computed independently
        float denom = fmaf(a, e, -bb * bb);
        float s = __saturatef(fmaf(bb, f, -c * e) * rcp_approx(denom));

        float t   = fmaf(bb, s, f) * inv_e;
        float t_c = __saturatef(t);
        float s_adj = __saturatef(fmaf(bb, t_c, -c) * inv_a);
        s = (t != t_c) ? s_adj : s;

        float c1x = fmaf(d1x, s, sx);
        float c1y = fmaf(d1y, s, sy);
        float c2x = fmaf(d2x, t_c, p2x);
        float c2y = fmaf(d2y, t_c, p2y);
        float c2z = fmaf(d2z, t_c, p2z);

        float dx = c1x - c2x;
        float dy = c1y - c2y;
        float dist = sqrt_approx(fmaf(dx, dx, fmaf(dy, dy, fmaf(c2z, c2z, 1e-12f))));

        mind = fminf(mind, dist - pr);
    }

    mind -= robot_radii[lane];   // lane-constant offset folded out of the loop

    // ---- warp min-reduce over lanes (links) ----
    #pragma unroll
    for (int off = 16; off > 0; off >>= 1)
        mind = fminf(mind, __shfl_xor_sync(FULL, mind, off));

    if (lane == 0) {
        float lam = __expf(log_lambda[0]);
        float magnitude = lam * (D_LIMIT - mind);
        out_penalty[b] = (mind < D_LIMIT) ? magnitude : 0.0f;
        out_mind[b]    = mind;
    }
}

extern "C" void kernel_launch(void* const* d_in, const int* in_sizes, int n_in,
                              void* d_out, int out_size)
{
    const float* joint_state    = (const float*)d_in[0];
    const float* action_nominal = (const float*)d_in[1];
    const float* link_lengths   = (const float*)d_in[2];
    const float* robot_radii    = (const float*)d_in[3];
    const float* p_start        = (const float*)d_in[4];
    const float* p_end          = (const float*)d_in[5];
    const float* p_radii        = (const float*)d_in[6];
    const float* log_lambda     = (const float*)d_in[7];

    const int R = 32;
    int B = in_sizes[0] / R;   // 8192

    float* out = (float*)d_out;
    float* out_action  = out;                      // [B,R]
    float* out_penalty = out + (size_t)B * R;      // [B]
    float* out_mind    = out + (size_t)B * R + B;  // [B]

    int blocks = (B + WARPS_PER_BLOCK - 1) / WARPS_PER_BLOCK;   // 1024
    safety_layer_kernel<<<blocks, WARPS_PER_BLOCK * 32>>>(
        joint_state, action_nominal, link_lengths, robot_radii,
        p_start, p_end, p_radii, log_lambda,
        out_action, out_penalty, out_mind);
}